// round 1
// baseline (speedup 1.0000x reference)
#include <cuda_runtime.h>
#include <math.h>
#include <stdint.h>

#define B_  4
#define T_  2048
#define C_  2048
#define NH  16
#define NKV 4
#define HD  128

// Scratch (allocation-free rule: __device__ globals)
__device__ float g_q[(size_t)B_ * T_ * C_];          // 64 MB
__device__ float g_k[(size_t)B_ * T_ * NKV * HD];    // 16 MB
__device__ float g_v[(size_t)B_ * T_ * NKV * HD];    // 16 MB
__device__ float g_y[(size_t)B_ * T_ * C_];          // 64 MB

// ---------------------------------------------------------------------------
// SGEMM: C[M,N] = A[M,K] @ B[K,N], row-major. 128x128 blocktile, BK=8,
// 256 threads, 8x8 microtile, float4 loads. Requires M%128==0, N%128==0, K%8==0.
// ---------------------------------------------------------------------------
__global__ __launch_bounds__(256) void sgemm128(
    const float* __restrict__ A, const float* __restrict__ Bm,
    float* __restrict__ Cm, int M, int N, int K)
{
    __shared__ float As[8][128];
    __shared__ float Bs[8][128];

    const int tid = threadIdx.x;
    const int bx = blockIdx.x, by = blockIdx.y;

    const float* Ab = A + (size_t)by * 128 * K;
    const float* Bb = Bm + (size_t)bx * 128;

    const int arow = tid >> 1;            // 0..127
    const int acol = (tid & 1) * 4;       // 0 or 4
    const int brow = tid >> 5;            // 0..7
    const int bcol = (tid & 31) * 4;      // 0..124
    const int tr = tid >> 4;              // 0..15
    const int tc = tid & 15;              // 0..15

    float acc[8][8];
#pragma unroll
    for (int i = 0; i < 8; i++)
#pragma unroll
        for (int j = 0; j < 8; j++) acc[i][j] = 0.0f;

    for (int k0 = 0; k0 < K; k0 += 8) {
        float4 a4 = *(const float4*)(Ab + (size_t)arow * K + k0 + acol);
        As[acol + 0][arow] = a4.x;
        As[acol + 1][arow] = a4.y;
        As[acol + 2][arow] = a4.z;
        As[acol + 3][arow] = a4.w;
        float4 b4 = *(const float4*)(Bb + (size_t)(k0 + brow) * N + bcol);
        *(float4*)&Bs[brow][bcol] = b4;
        __syncthreads();

#pragma unroll
        for (int k = 0; k < 8; k++) {
            float4 a0 = *(const float4*)&As[k][tr * 8];
            float4 a1 = *(const float4*)&As[k][tr * 8 + 4];
            float4 b0 = *(const float4*)&Bs[k][tc * 8];
            float4 b1 = *(const float4*)&Bs[k][tc * 8 + 4];
            float ra[8] = {a0.x, a0.y, a0.z, a0.w, a1.x, a1.y, a1.z, a1.w};
            float rb[8] = {b0.x, b0.y, b0.z, b0.w, b1.x, b1.y, b1.z, b1.w};
#pragma unroll
            for (int i = 0; i < 8; i++)
#pragma unroll
                for (int j = 0; j < 8; j++)
                    acc[i][j] += ra[i] * rb[j];
        }
        __syncthreads();
    }

#pragma unroll
    for (int i = 0; i < 8; i++) {
        float* crow = Cm + (size_t)(by * 128 + tr * 8 + i) * N + bx * 128 + tc * 8;
        float4 c0 = {acc[i][0], acc[i][1], acc[i][2], acc[i][3]};
        float4 c1 = {acc[i][4], acc[i][5], acc[i][6], acc[i][7]};
        *(float4*)(crow)     = c0;
        *(float4*)(crow + 4) = c1;
    }
}

// ---------------------------------------------------------------------------
// RoPE, in place, matching the reference exactly:
//   out[j]      = x[j]*cos(a_j)      - x[j+64]*sin(a_j)        (j < 64)
//   out[j+64]   = x[j+64]*cos(a_j64) + x[j]*sin(a_j64)
//   a_j = (pos+t) * 10000^{-(2*(j>>1))/128}
// One thread per (row, head, pair).
// ---------------------------------------------------------------------------
__global__ void rope_kernel(float* __restrict__ X, const int* __restrict__ posp,
                            int nheads, int total)
{
    int idx = blockIdx.x * blockDim.x + threadIdx.x;
    if (idx >= total) return;
    int p   = idx & 63;
    int h   = (idx >> 6) % nheads;
    int row = idx / (64 * nheads);       // b*T + t
    int t   = row % T_;
    float pos = (float)(posp[0] + t);

    float* base = X + (size_t)row * (nheads * HD) + h * HD;
    float x1 = base[p];
    float x2 = base[p + 64];

    const float LN1E4 = 9.210340371976184f;  // ln(10000)
    float e1 = (float)(2 * (p >> 1)) * (1.0f / 128.0f);
    float e2 = e1 + 0.5f;                    // + 64/128
    float f1 = __expf(-e1 * LN1E4);
    float f2 = __expf(-e2 * LN1E4);
    float a1 = pos * f1;
    float a2 = pos * f2;

    float o1 = x1 * cosf(a1) - x2 * sinf(a1);
    float o2 = x2 * cosf(a2) + x1 * sinf(a2);
    base[p]      = o1;
    base[p + 64] = o2;
}

// ---------------------------------------------------------------------------
// Flash attention fp32. 64 queries x 64 keys per tile, D=128.
// 256 threads: thread (ty,tx), ty=tid>>4, tx=tid&15.
//  S microtile: 4 rows (ty*4..) x 4 cols (tx, tx+16, tx+32, tx+48)
//  O microtile: 4 rows x 8 d-cols (tx*8..)
// Row stats m/l live in registers; 16-lane shfl reductions (row group = half warp).
// ---------------------------------------------------------------------------
#define QPAD 132
#define PPAD 65
#define FLASH_SMEM ((3 * 64 * QPAD + 64 * PPAD) * 4)

extern __shared__ float fsm[];

__global__ __launch_bounds__(256) void flash_kernel(
    const float* __restrict__ Q, const float* __restrict__ Kg,
    const float* __restrict__ Vg, float* __restrict__ Y)
{
    float* Qs = fsm;
    float* Ks = Qs + 64 * QPAD;
    float* Vs = Ks + 64 * QPAD;
    float* Ps = Vs + 64 * QPAD;

    const int tid = threadIdx.x;
    const int qt = blockIdx.x, h = blockIdx.y, b = blockIdx.z;
    const int kvh = h >> 2;
    const int ty = tid >> 4, tx = tid & 15;

    const int qstride = C_;          // 2048
    const int kstride = NKV * HD;    // 512

    const float* Qb = Q  + ((size_t)b * T_ + (size_t)qt * 64) * qstride + h * HD;
    const float* Kb = Kg + ((size_t)b * T_) * kstride + kvh * HD;
    const float* Vb = Vg + ((size_t)b * T_) * kstride + kvh * HD;

    // load Q tile (64 x 128)
    for (int i = tid; i < 64 * 32; i += 256) {
        int r = i >> 5, c4 = (i & 31) << 2;
        *(float4*)&Qs[r * QPAD + c4] = *(const float4*)(Qb + (size_t)r * qstride + c4);
    }

    float m[4], l[4], o[4][8];
#pragma unroll
    for (int r = 0; r < 4; r++) {
        m[r] = -INFINITY; l[r] = 0.0f;
#pragma unroll
        for (int c = 0; c < 8; c++) o[r][c] = 0.0f;
    }

    const float scale = 0.08838834764831845f;  // 1/sqrt(128)
    const int qg0 = qt * 64 + ty * 4;

    for (int kt = 0; kt <= qt; ++kt) {
        const float* Kt = Kb + (size_t)kt * 64 * kstride;
        const float* Vt = Vb + (size_t)kt * 64 * kstride;
        for (int i = tid; i < 64 * 32; i += 256) {
            int r = i >> 5, c4 = (i & 31) << 2;
            *(float4*)&Ks[r * QPAD + c4] = *(const float4*)(Kt + (size_t)r * kstride + c4);
            *(float4*)&Vs[r * QPAD + c4] = *(const float4*)(Vt + (size_t)r * kstride + c4);
        }
        __syncthreads();

        // S = Q K^T  (4x4 microtile)
        float s[4][4];
#pragma unroll
        for (int r = 0; r < 4; r++)
#pragma unroll
            for (int c = 0; c < 4; c++) s[r][c] = 0.0f;

        for (int k4 = 0; k4 < 128; k4 += 4) {
            float4 qv[4], kv[4];
#pragma unroll
            for (int r = 0; r < 4; r++)
                qv[r] = *(const float4*)&Qs[(ty * 4 + r) * QPAD + k4];
#pragma unroll
            for (int ci = 0; ci < 4; ci++)
                kv[ci] = *(const float4*)&Ks[(tx + 16 * ci) * QPAD + k4];
#pragma unroll
            for (int r = 0; r < 4; r++)
#pragma unroll
                for (int ci = 0; ci < 4; ci++)
                    s[r][ci] += qv[r].x * kv[ci].x + qv[r].y * kv[ci].y
                              + qv[r].z * kv[ci].z + qv[r].w * kv[ci].w;
        }

        // scale + causal mask
        const int kg0 = kt * 64;
#pragma unroll
        for (int r = 0; r < 4; r++)
#pragma unroll
            for (int ci = 0; ci < 4; ci++) {
                int kg = kg0 + tx + 16 * ci;
                s[r][ci] = (kg <= qg0 + r) ? s[r][ci] * scale : -1e30f;
            }

        // online softmax per row (reduce across 16 lanes sharing the row)
#pragma unroll
        for (int r = 0; r < 4; r++) {
            float tm = fmaxf(fmaxf(s[r][0], s[r][1]), fmaxf(s[r][2], s[r][3]));
#pragma unroll
            for (int off = 8; off > 0; off >>= 1)
                tm = fmaxf(tm, __shfl_xor_sync(0xffffffffu, tm, off));
            float mn = fmaxf(m[r], tm);
            float fac = __expf(m[r] - mn);
            float ts = 0.0f;
#pragma unroll
            for (int ci = 0; ci < 4; ci++) {
                float p = __expf(s[r][ci] - mn);
                s[r][ci] = p;
                ts += p;
            }
#pragma unroll
            for (int off = 8; off > 0; off >>= 1)
                ts += __shfl_xor_sync(0xffffffffu, ts, off);
            l[r] = l[r] * fac + ts;
            m[r] = mn;
#pragma unroll
            for (int c = 0; c < 8; c++) o[r][c] *= fac;
#pragma unroll
            for (int ci = 0; ci < 4; ci++)
                Ps[(ty * 4 + r) * PPAD + tx + 16 * ci] = s[r][ci];
        }
        __syncthreads();

        // O += P @ V
        for (int kk = 0; kk < 64; kk++) {
            float pr[4];
#pragma unroll
            for (int r = 0; r < 4; r++) pr[r] = Ps[(ty * 4 + r) * PPAD + kk];
            float4 v0 = *(const float4*)&Vs[kk * QPAD + tx * 8];
            float4 v1 = *(const float4*)&Vs[kk * QPAD + tx * 8 + 4];
#pragma unroll
            for (int r = 0; r < 4; r++) {
                o[r][0] += pr[r] * v0.x;  o[r][1] += pr[r] * v0.y;
                o[r][2] += pr[r] * v0.z;  o[r][3] += pr[r] * v0.w;
                o[r][4] += pr[r] * v1.x;  o[r][5] += pr[r] * v1.y;
                o[r][6] += pr[r] * v1.z;  o[r][7] += pr[r] * v1.w;
            }
        }
        __syncthreads();
    }

    // normalize + store
#pragma unroll
    for (int r = 0; r < 4; r++) {
        float inv = 1.0f / l[r];
        float* dst = Y + ((size_t)b * T_ + (size_t)(qt * 64 + ty * 4 + r)) * C_
                       + h * HD + tx * 8;
        float4 w0 = {o[r][0] * inv, o[r][1] * inv, o[r][2] * inv, o[r][3] * inv};
        float4 w1 = {o[r][4] * inv, o[r][5] * inv, o[r][6] * inv, o[r][7] * inv};
        *(float4*)(dst)     = w0;
        *(float4*)(dst + 4) = w1;
    }
}

// ---------------------------------------------------------------------------
extern "C" void kernel_launch(void* const* d_in, const int* in_sizes, int n_in,
                              void* d_out, int out_size)
{
    const float* x  = (const float*)d_in[0];
    const float* Wq = (const float*)d_in[1];
    const float* Wk = (const float*)d_in[2];
    const float* Wv = (const float*)d_in[3];
    const float* Wo = (const float*)d_in[4];
    const int*  pos = (const int*)d_in[5];
    float* out = (float*)d_out;

    float *q, *k, *v, *y;
    cudaGetSymbolAddress((void**)&q, g_q);
    cudaGetSymbolAddress((void**)&k, g_k);
    cudaGetSymbolAddress((void**)&v, g_v);
    cudaGetSymbolAddress((void**)&y, g_y);

    const int M = B_ * T_;   // 8192

    // Projections
    sgemm128<<<dim3(C_ / 128, M / 128), 256>>>(x, Wq, q, M, C_, C_);
    sgemm128<<<dim3((NKV * HD) / 128, M / 128), 256>>>(x, Wk, k, M, NKV * HD, C_);
    sgemm128<<<dim3((NKV * HD) / 128, M / 128), 256>>>(x, Wv, v, M, NKV * HD, C_);

    // RoPE on q and k
    int qp = M * NH * 64;
    rope_kernel<<<(qp + 255) / 256, 256>>>(q, pos, NH, qp);
    int kp = M * NKV * 64;
    rope_kernel<<<(kp + 255) / 256, 256>>>(k, pos, NKV, kp);

    // Flash attention
    cudaFuncSetAttribute(flash_kernel, cudaFuncAttributeMaxDynamicSharedMemorySize,
                         FLASH_SMEM);
    flash_kernel<<<dim3(T_ / 64, NH, B_), 256, FLASH_SMEM>>>(q, k, v, y);

    // Output projection
    sgemm128<<<dim3(C_ / 128, M / 128), 256>>>(y, Wo, out, M, C_, C_);
}

// round 2
// speedup vs baseline: 1.0838x; 1.0838x over previous
#include <cuda_runtime.h>
#include <math.h>
#include <stdint.h>

#define B_  4
#define T_  2048
#define C_  2048
#define NH  16
#define NKV 4
#define HD  128

// Scratch (allocation-free rule: __device__ globals)
__device__ float g_q[(size_t)B_ * T_ * C_];          // 64 MB
__device__ float g_k[(size_t)B_ * T_ * NKV * HD];    // 16 MB
__device__ float g_v[(size_t)B_ * T_ * NKV * HD];    // 16 MB
__device__ float g_y[(size_t)B_ * T_ * C_];          // 64 MB

// ---- packed f32x2 helpers (sm_103a FFMA2 path; ptxas never auto-fuses) ----
typedef unsigned long long u64;

__device__ __forceinline__ u64 pack2(float lo, float hi) {
    u64 r;
    asm("mov.b64 %0, {%1, %2};" : "=l"(r) : "f"(lo), "f"(hi));
    return r;
}
__device__ __forceinline__ void unpack2(u64 v, float& lo, float& hi) {
    asm("mov.b64 {%0, %1}, %2;" : "=f"(lo), "=f"(hi) : "l"(v));
}
__device__ __forceinline__ void fma2(u64& d, u64 a, u64 b) {
    asm("fma.rn.f32x2 %0, %1, %2, %0;" : "+l"(d) : "l"(a), "l"(b));
}
__device__ __forceinline__ void mul2(u64& d, u64 a) {
    asm("mul.rn.f32x2 %0, %0, %1;" : "+l"(d) : "l"(a));
}

// ---------------------------------------------------------------------------
// SGEMM: C[M,N] = A[M,K] @ B[K,N], row-major. 128x128 blocktile, BK=8,
// 256 threads, 8x8 microtile (accumulators packed 2-wide), float4 loads.
// ---------------------------------------------------------------------------
__global__ __launch_bounds__(256) void sgemm128(
    const float* __restrict__ A, const float* __restrict__ Bm,
    float* __restrict__ Cm, int M, int N, int K)
{
    __shared__ float As[8][128];
    __shared__ float Bs[8][128];

    const int tid = threadIdx.x;
    const int bx = blockIdx.x, by = blockIdx.y;

    const float* Ab = A + (size_t)by * 128 * K;
    const float* Bb = Bm + (size_t)bx * 128;

    const int arow = tid >> 1;
    const int acol = (tid & 1) * 4;
    const int brow = tid >> 5;
    const int bcol = (tid & 31) * 4;
    const int tr = tid >> 4;
    const int tc = tid & 15;

    u64 acc[8][4];
#pragma unroll
    for (int i = 0; i < 8; i++)
#pragma unroll
        for (int j = 0; j < 4; j++) acc[i][j] = 0ull;

    for (int k0 = 0; k0 < K; k0 += 8) {
        float4 a4 = *(const float4*)(Ab + (size_t)arow * K + k0 + acol);
        As[acol + 0][arow] = a4.x;
        As[acol + 1][arow] = a4.y;
        As[acol + 2][arow] = a4.z;
        As[acol + 3][arow] = a4.w;
        float4 b4 = *(const float4*)(Bb + (size_t)(k0 + brow) * N + bcol);
        *(float4*)&Bs[brow][bcol] = b4;
        __syncthreads();

#pragma unroll
        for (int k = 0; k < 8; k++) {
            float4 a0 = *(const float4*)&As[k][tr * 8];
            float4 a1 = *(const float4*)&As[k][tr * 8 + 4];
            float4 b0 = *(const float4*)&Bs[k][tc * 8];
            float4 b1 = *(const float4*)&Bs[k][tc * 8 + 4];
            u64 bb[4];
            bb[0] = pack2(b0.x, b0.y);
            bb[1] = pack2(b0.z, b0.w);
            bb[2] = pack2(b1.x, b1.y);
            bb[3] = pack2(b1.z, b1.w);
            float ra[8] = {a0.x, a0.y, a0.z, a0.w, a1.x, a1.y, a1.z, a1.w};
#pragma unroll
            for (int i = 0; i < 8; i++) {
                u64 aa = pack2(ra[i], ra[i]);
                fma2(acc[i][0], aa, bb[0]);
                fma2(acc[i][1], aa, bb[1]);
                fma2(acc[i][2], aa, bb[2]);
                fma2(acc[i][3], aa, bb[3]);
            }
        }
        __syncthreads();
    }

#pragma unroll
    for (int i = 0; i < 8; i++) {
        float* crow = Cm + (size_t)(by * 128 + tr * 8 + i) * N + bx * 128 + tc * 8;
        float4 c0, c1;
        unpack2(acc[i][0], c0.x, c0.y);
        unpack2(acc[i][1], c0.z, c0.w);
        unpack2(acc[i][2], c1.x, c1.y);
        unpack2(acc[i][3], c1.z, c1.w);
        *(float4*)(crow)     = c0;
        *(float4*)(crow + 4) = c1;
    }
}

// ---------------------------------------------------------------------------
// RoPE, in place, matching the reference exactly.
// ---------------------------------------------------------------------------
__global__ void rope_kernel(float* __restrict__ X, const int* __restrict__ posp,
                            int nheads, int total)
{
    int idx = blockIdx.x * blockDim.x + threadIdx.x;
    if (idx >= total) return;
    int p   = idx & 63;
    int h   = (idx >> 6) % nheads;
    int row = idx / (64 * nheads);       // b*T + t
    int t   = row % T_;
    float pos = (float)(posp[0] + t);

    float* base = X + (size_t)row * (nheads * HD) + h * HD;
    float x1 = base[p];
    float x2 = base[p + 64];

    const float LN1E4 = 9.210340371976184f;  // ln(10000)
    float e1 = (float)(2 * (p >> 1)) * (1.0f / 128.0f);
    float e2 = e1 + 0.5f;
    float f1 = __expf(-e1 * LN1E4);
    float f2 = __expf(-e2 * LN1E4);
    float a1 = pos * f1;
    float a2 = pos * f2;

    float o1 = x1 * cosf(a1) - x2 * sinf(a1);
    float o2 = x2 * cosf(a2) + x1 * sinf(a2);
    base[p]      = o1;
    base[p + 64] = o2;
}

// ---------------------------------------------------------------------------
// Flash attention fp32 with packed f32x2 FMAs.
// 64 queries x 64 keys per tile, D=128. 256 threads, (ty,tx)=16x16.
//  S microtile: 4 rows x 4 cols (tx + 16*ci); O microtile: 4 rows x 8 d-cols.
// ---------------------------------------------------------------------------
#define QPAD 132
#define PPAD 65
#define FLASH_SMEM ((3 * 64 * QPAD + 64 * PPAD) * 4)

extern __shared__ float fsm[];

__global__ __launch_bounds__(256) void flash_kernel(
    const float* __restrict__ Q, const float* __restrict__ Kg,
    const float* __restrict__ Vg, float* __restrict__ Y)
{
    float* Qs = fsm;
    float* Ks = Qs + 64 * QPAD;
    float* Vs = Ks + 64 * QPAD;
    float* Ps = Vs + 64 * QPAD;

    const int tid = threadIdx.x;
    const int qt = blockIdx.x, h = blockIdx.y, b = blockIdx.z;
    const int kvh = h >> 2;
    const int ty = tid >> 4, tx = tid & 15;

    const int qstride = C_;          // 2048
    const int kstride = NKV * HD;    // 512

    const float* Qb = Q  + ((size_t)b * T_ + (size_t)qt * 64) * qstride + h * HD;
    const float* Kb = Kg + ((size_t)b * T_) * kstride + kvh * HD;
    const float* Vb = Vg + ((size_t)b * T_) * kstride + kvh * HD;

    for (int i = tid; i < 64 * 32; i += 256) {
        int r = i >> 5, c4 = (i & 31) << 2;
        *(float4*)&Qs[r * QPAD + c4] = *(const float4*)(Qb + (size_t)r * qstride + c4);
    }

    float m[4], l[4];
    u64 o2[4][4];                    // 4 rows x 8 d-cols packed pairwise
#pragma unroll
    for (int r = 0; r < 4; r++) {
        m[r] = -INFINITY; l[r] = 0.0f;
#pragma unroll
        for (int c = 0; c < 4; c++) o2[r][c] = 0ull;
    }

    const float scale = 0.08838834764831845f;  // 1/sqrt(128)
    const int qg0 = qt * 64 + ty * 4;

    for (int kt = 0; kt <= qt; ++kt) {
        const float* Kt = Kb + (size_t)kt * 64 * kstride;
        const float* Vt = Vb + (size_t)kt * 64 * kstride;
        for (int i = tid; i < 64 * 32; i += 256) {
            int r = i >> 5, c4 = (i & 31) << 2;
            *(float4*)&Ks[r * QPAD + c4] = *(const float4*)(Kt + (size_t)r * kstride + c4);
            *(float4*)&Vs[r * QPAD + c4] = *(const float4*)(Vt + (size_t)r * kstride + c4);
        }
        __syncthreads();

        // S = Q K^T, packed pairwise along k (two partial sums per cell)
        u64 s2[4][4];
#pragma unroll
        for (int r = 0; r < 4; r++)
#pragma unroll
            for (int c = 0; c < 4; c++) s2[r][c] = 0ull;

        for (int k4 = 0; k4 < 128; k4 += 4) {
            u64 qp[4][2], kp[4][2];
#pragma unroll
            for (int r = 0; r < 4; r++) {
                float4 qv = *(const float4*)&Qs[(ty * 4 + r) * QPAD + k4];
                qp[r][0] = pack2(qv.x, qv.y);
                qp[r][1] = pack2(qv.z, qv.w);
            }
#pragma unroll
            for (int ci = 0; ci < 4; ci++) {
                float4 kv = *(const float4*)&Ks[(tx + 16 * ci) * QPAD + k4];
                kp[ci][0] = pack2(kv.x, kv.y);
                kp[ci][1] = pack2(kv.z, kv.w);
            }
#pragma unroll
            for (int r = 0; r < 4; r++)
#pragma unroll
                for (int ci = 0; ci < 4; ci++) {
                    fma2(s2[r][ci], qp[r][0], kp[ci][0]);
                    fma2(s2[r][ci], qp[r][1], kp[ci][1]);
                }
        }

        // horizontal add + scale + causal mask
        float s[4][4];
        const int kg0 = kt * 64;
#pragma unroll
        for (int r = 0; r < 4; r++)
#pragma unroll
            for (int ci = 0; ci < 4; ci++) {
                float lo, hi;
                unpack2(s2[r][ci], lo, hi);
                int kg = kg0 + tx + 16 * ci;
                s[r][ci] = (kg <= qg0 + r) ? (lo + hi) * scale : -1e30f;
            }

        // online softmax per row (16-lane shfl reduction)
#pragma unroll
        for (int r = 0; r < 4; r++) {
            float tm = fmaxf(fmaxf(s[r][0], s[r][1]), fmaxf(s[r][2], s[r][3]));
#pragma unroll
            for (int off = 8; off > 0; off >>= 1)
                tm = fmaxf(tm, __shfl_xor_sync(0xffffffffu, tm, off));
            float mn = fmaxf(m[r], tm);
            float fac = __expf(m[r] - mn);
            float ts = 0.0f;
#pragma unroll
            for (int ci = 0; ci < 4; ci++) {
                float p = __expf(s[r][ci] - mn);
                s[r][ci] = p;
                ts += p;
            }
#pragma unroll
            for (int off = 8; off > 0; off >>= 1)
                ts += __shfl_xor_sync(0xffffffffu, ts, off);
            l[r] = l[r] * fac + ts;
            m[r] = mn;
            u64 facp = pack2(fac, fac);
#pragma unroll
            for (int c = 0; c < 4; c++) mul2(o2[r][c], facp);
#pragma unroll
            for (int ci = 0; ci < 4; ci++)
                Ps[(ty * 4 + r) * PPAD + tx + 16 * ci] = s[r][ci];
        }
        __syncthreads();

        // O += P @ V   (packed over d)
        for (int kk = 0; kk < 64; kk++) {
            u64 pp[4];
#pragma unroll
            for (int r = 0; r < 4; r++) {
                float p = Ps[(ty * 4 + r) * PPAD + kk];
                pp[r] = pack2(p, p);
            }
            float4 v0 = *(const float4*)&Vs[kk * QPAD + tx * 8];
            float4 v1 = *(const float4*)&Vs[kk * QPAD + tx * 8 + 4];
            u64 vv[4];
            vv[0] = pack2(v0.x, v0.y);
            vv[1] = pack2(v0.z, v0.w);
            vv[2] = pack2(v1.x, v1.y);
            vv[3] = pack2(v1.z, v1.w);
#pragma unroll
            for (int r = 0; r < 4; r++) {
                fma2(o2[r][0], pp[r], vv[0]);
                fma2(o2[r][1], pp[r], vv[1]);
                fma2(o2[r][2], pp[r], vv[2]);
                fma2(o2[r][3], pp[r], vv[3]);
            }
        }
        __syncthreads();
    }

    // normalize + store
#pragma unroll
    for (int r = 0; r < 4; r++) {
        float inv = 1.0f / l[r];
        u64 invp = pack2(inv, inv);
        float* dst = Y + ((size_t)b * T_ + (size_t)(qt * 64 + ty * 4 + r)) * C_
                       + h * HD + tx * 8;
        float4 w0, w1;
        mul2(o2[r][0], invp); mul2(o2[r][1], invp);
        mul2(o2[r][2], invp); mul2(o2[r][3], invp);
        unpack2(o2[r][0], w0.x, w0.y);
        unpack2(o2[r][1], w0.z, w0.w);
        unpack2(o2[r][2], w1.x, w1.y);
        unpack2(o2[r][3], w1.z, w1.w);
        *(float4*)(dst)     = w0;
        *(float4*)(dst + 4) = w1;
    }
}

// ---------------------------------------------------------------------------
extern "C" void kernel_launch(void* const* d_in, const int* in_sizes, int n_in,
                              void* d_out, int out_size)
{
    const float* x  = (const float*)d_in[0];
    const float* Wq = (const float*)d_in[1];
    const float* Wk = (const float*)d_in[2];
    const float* Wv = (const float*)d_in[3];
    const float* Wo = (const float*)d_in[4];
    const int*  pos = (const int*)d_in[5];
    float* out = (float*)d_out;

    float *q, *k, *v, *y;
    cudaGetSymbolAddress((void**)&q, g_q);
    cudaGetSymbolAddress((void**)&k, g_k);
    cudaGetSymbolAddress((void**)&v, g_v);
    cudaGetSymbolAddress((void**)&y, g_y);

    const int M = B_ * T_;   // 8192

    // Projections
    sgemm128<<<dim3(C_ / 128, M / 128), 256>>>(x, Wq, q, M, C_, C_);
    sgemm128<<<dim3((NKV * HD) / 128, M / 128), 256>>>(x, Wk, k, M, NKV * HD, C_);
    sgemm128<<<dim3((NKV * HD) / 128, M / 128), 256>>>(x, Wv, v, M, NKV * HD, C_);

    // RoPE on q and k
    int qp = M * NH * 64;
    rope_kernel<<<(qp + 255) / 256, 256>>>(q, pos, NH, qp);
    int kp = M * NKV * 64;
    rope_kernel<<<(kp + 255) / 256, 256>>>(k, pos, NKV, kp);

    // Flash attention
    cudaFuncSetAttribute(flash_kernel, cudaFuncAttributeMaxDynamicSharedMemorySize,
                         FLASH_SMEM);
    flash_kernel<<<dim3(T_ / 64, NH, B_), 256, FLASH_SMEM>>>(q, k, v, y);

    // Output projection
    sgemm128<<<dim3(C_ / 128, M / 128), 256>>>(y, Wo, out, M, C_, C_);
}

// round 4
// speedup vs baseline: 1.6570x; 1.5289x over previous
#include <cuda_runtime.h>
#include <cuda_bf16.h>
#include <math.h>
#include <stdint.h>

typedef unsigned long long u64;

#define B_   4
#define T_   2048
#define C_   2048
#define NH   16
#define NKV  4
#define HD   128
#define KVD  (NKV*HD)   // 512
#define M_   (B_*T_)    // 8192

// ---------------- scratch (__device__ globals; no allocs allowed) ----------
__device__ float g_q[(size_t)M_ * C_];
__device__ float g_k[(size_t)M_ * KVD];
__device__ float g_v[(size_t)M_ * KVD];
__device__ float g_y[(size_t)M_ * C_];

__device__ __nv_bfloat16 s_xh[(size_t)M_ * C_],  s_xl[(size_t)M_ * C_];
__device__ __nv_bfloat16 s_yh[(size_t)M_ * C_],  s_yl[(size_t)M_ * C_];
__device__ __nv_bfloat16 s_wqh[(size_t)C_ * C_], s_wql[(size_t)C_ * C_];
__device__ __nv_bfloat16 s_wkh[(size_t)KVD * C_], s_wkl[(size_t)KVD * C_];
__device__ __nv_bfloat16 s_wvh[(size_t)KVD * C_], s_wvl[(size_t)KVD * C_];
__device__ __nv_bfloat16 s_woh[(size_t)C_ * C_], s_wol[(size_t)C_ * C_];

// ---------------- helpers ---------------------------------------------------
__device__ __forceinline__ uint32_t smem_u32(const void* p) {
    uint32_t a;
    asm("{ .reg .u64 t; cvta.to.shared.u64 t, %1; cvt.u32.u64 %0, t; }"
        : "=r"(a) : "l"(p));
    return a;
}
__device__ __forceinline__ void ldsm4(uint32_t* r, uint32_t addr) {
    asm volatile("ldmatrix.sync.aligned.m8n8.x4.shared.b16 {%0,%1,%2,%3}, [%4];"
                 : "=r"(r[0]), "=r"(r[1]), "=r"(r[2]), "=r"(r[3]) : "r"(addr));
}
__device__ __forceinline__ void mma16816(float* c, const uint32_t* a,
                                         const uint32_t* b) {
    asm volatile(
        "mma.sync.aligned.m16n8k16.row.col.f32.bf16.bf16.f32 "
        "{%0,%1,%2,%3}, {%4,%5,%6,%7}, {%8,%9}, {%0,%1,%2,%3};"
        : "+f"(c[0]), "+f"(c[1]), "+f"(c[2]), "+f"(c[3])
        : "r"(a[0]), "r"(a[1]), "r"(a[2]), "r"(a[3]), "r"(b[0]), "r"(b[1]));
}

// ---- packed f32x2 helpers (flash kernel) ----
__device__ __forceinline__ u64 pack2(float lo, float hi) {
    u64 r; asm("mov.b64 %0, {%1, %2};" : "=l"(r) : "f"(lo), "f"(hi)); return r;
}
__device__ __forceinline__ void unpack2(u64 v, float& lo, float& hi) {
    asm("mov.b64 {%0, %1}, %2;" : "=f"(lo), "=f"(hi) : "l"(v));
}
__device__ __forceinline__ void fma2(u64& d, u64 a, u64 b) {
    asm("fma.rn.f32x2 %0, %1, %2, %0;" : "+l"(d) : "l"(a), "l"(b));
}
__device__ __forceinline__ void mul2(u64& d, u64 a) {
    asm("mul.rn.f32x2 %0, %0, %1;" : "+l"(d) : "l"(a));
}

// ---------------------------------------------------------------------------
// split: fp32 -> (bf16 hi, bf16 lo), vectorized x4
// ---------------------------------------------------------------------------
__global__ void split_kernel(const float* __restrict__ X,
                             __nv_bfloat16* __restrict__ H,
                             __nv_bfloat16* __restrict__ L, int n4)
{
    int i = blockIdx.x * blockDim.x + threadIdx.x;
    if (i >= n4) return;
    float4 v = ((const float4*)X)[i];
    float vv[4] = {v.x, v.y, v.z, v.w};
    __nv_bfloat162 h0, h1, l0, l1;
    __nv_bfloat16 h[4], l[4];
#pragma unroll
    for (int j = 0; j < 4; j++) {
        h[j] = __float2bfloat16(vv[j]);
        l[j] = __float2bfloat16(vv[j] - __bfloat162float(h[j]));
    }
    h0.x = h[0]; h0.y = h[1]; h1.x = h[2]; h1.y = h[3];
    l0.x = l[0]; l0.y = l[1]; l1.x = l[2]; l1.y = l[3];
    ((__nv_bfloat162*)H)[2 * i]     = h0;
    ((__nv_bfloat162*)H)[2 * i + 1] = h1;
    ((__nv_bfloat162*)L)[2 * i]     = l0;
    ((__nv_bfloat162*)L)[2 * i + 1] = l1;
}

// ---------------------------------------------------------------------------
// transpose + split: W[K,N] fp32 -> Th/Tl [N,K] bf16
// ---------------------------------------------------------------------------
__global__ void transpose_split_kernel(const float* __restrict__ W,
                                       __nv_bfloat16* __restrict__ Th,
                                       __nv_bfloat16* __restrict__ Tl,
                                       int K, int N)
{
    __shared__ float t[32][33];
    int n0 = blockIdx.x * 32, k0 = blockIdx.y * 32;
    int tx = threadIdx.x, ty = threadIdx.y;  // 32 x 8
#pragma unroll
    for (int j = 0; j < 4; j++)
        t[ty + 8 * j][tx] = W[(size_t)(k0 + ty + 8 * j) * N + n0 + tx];
    __syncthreads();
#pragma unroll
    for (int j = 0; j < 4; j++) {
        float v = t[tx][ty + 8 * j];
        __nv_bfloat16 h = __float2bfloat16(v);
        __nv_bfloat16 l = __float2bfloat16(v - __bfloat162float(h));
        size_t o = (size_t)(n0 + ty + 8 * j) * K + k0 + tx;
        Th[o] = h;
        Tl[o] = l;
    }
}

// ---------------------------------------------------------------------------
// bf16-split GEMM via mma.sync (HMMA): C[M,N] = A[M,K] @ W[K,N] in fp32-grade.
// A split (Ah/Al [M,K]); W split+transposed (Bh/Bl [N,K]).
// CTA 128x128, BK=32, 8 warps (2m x 4n), warp tile 64x32, m16n8k16 frags.
// smem rows strided 40 bf16 (80B) -> conflict-free ldmatrix.
// ---------------------------------------------------------------------------
#define SAS 40   // smem row stride in bf16 elements

__global__ __launch_bounds__(256) void gemm_mma(
    const __nv_bfloat16* __restrict__ Ah, const __nv_bfloat16* __restrict__ Al,
    const __nv_bfloat16* __restrict__ Bh, const __nv_bfloat16* __restrict__ Bl,
    float* __restrict__ C, int N, int K)
{
    __shared__ __nv_bfloat16 sAh[128 * SAS], sAl[128 * SAS];
    __shared__ __nv_bfloat16 sBh[128 * SAS], sBl[128 * SAS];

    const int tid = threadIdx.x;
    const int lane = tid & 31, wid = tid >> 5;
    const int wm = wid & 1, wn = wid >> 1;       // 2 x 4 warp grid
    const int m0 = blockIdx.y * 128, n0 = blockIdx.x * 128;

    // ---- global->smem mapping: thread t loads 2 uint4 per buffer ----
    const int ldrow = tid >> 1, ldhalf = tid & 1;
    const __nv_bfloat16* gAh = Ah + (size_t)(m0 + ldrow) * K + ldhalf * 16;
    const __nv_bfloat16* gAl = Al + (size_t)(m0 + ldrow) * K + ldhalf * 16;
    const __nv_bfloat16* gBh = Bh + (size_t)(n0 + ldrow) * K + ldhalf * 16;
    const __nv_bfloat16* gBl = Bl + (size_t)(n0 + ldrow) * K + ldhalf * 16;
    char* stAh = (char*)sAh + (ldrow * SAS + ldhalf * 16) * 2;
    char* stAl = (char*)sAl + (ldrow * SAS + ldhalf * 16) * 2;
    char* stBh = (char*)sBh + (ldrow * SAS + ldhalf * 16) * 2;
    char* stBl = (char*)sBl + (ldrow * SAS + ldhalf * 16) * 2;

    // ---- ldmatrix per-thread addresses ----
    const int mid = lane >> 3, rin = lane & 7;
    const uint32_t aoff =
        ((wm * 64 + (mid & 1) * 8 + rin) * SAS + (mid >> 1) * 8) * 2;
    const uint32_t boff =
        ((wn * 32 + (mid >> 1) * 8 + rin) * SAS + (mid & 1) * 8) * 2;
    const uint32_t uAh = smem_u32(sAh) + aoff, uAl = smem_u32(sAl) + aoff;
    const uint32_t uBh = smem_u32(sBh) + boff, uBl = smem_u32(sBl) + boff;

    float acc[4][4][4];
#pragma unroll
    for (int mt = 0; mt < 4; mt++)
#pragma unroll
        for (int nt = 0; nt < 4; nt++)
#pragma unroll
            for (int j = 0; j < 4; j++) acc[mt][nt][j] = 0.0f;

    uint4 rah[2], ral[2], rbh[2], rbl[2];

#define GLOAD(k0)                                            \
    {                                                        \
        rah[0] = *(const uint4*)(gAh + (k0));                \
        rah[1] = *(const uint4*)(gAh + (k0) + 8);            \
        ral[0] = *(const uint4*)(gAl + (k0));                \
        ral[1] = *(const uint4*)(gAl + (k0) + 8);            \
        rbh[0] = *(const uint4*)(gBh + (k0));                \
        rbh[1] = *(const uint4*)(gBh + (k0) + 8);            \
        rbl[0] = *(const uint4*)(gBl + (k0));                \
        rbl[1] = *(const uint4*)(gBl + (k0) + 8);            \
    }
#define SSTORE()                                             \
    {                                                        \
        *(uint4*)(stAh) = rah[0]; *(uint4*)(stAh + 16) = rah[1]; \
        *(uint4*)(stAl) = ral[0]; *(uint4*)(stAl + 16) = ral[1]; \
        *(uint4*)(stBh) = rbh[0]; *(uint4*)(stBh + 16) = rbh[1]; \
        *(uint4*)(stBl) = rbl[0]; *(uint4*)(stBl + 16) = rbl[1]; \
    }

    GLOAD(0);
    SSTORE();
    __syncthreads();

    const int nch = K / 32;
    for (int ch = 0; ch < nch; ch++) {
        const bool more = (ch + 1 < nch);
        if (more) GLOAD((ch + 1) * 32);

#pragma unroll
        for (int ks = 0; ks < 2; ks++) {
            uint32_t fah[4][4], fal[4][4], fbh[2][4], fbl[2][4];
#pragma unroll
            for (int mt = 0; mt < 4; mt++) {
                ldsm4(fah[mt], uAh + mt * (16 * SAS * 2) + ks * 32);
                ldsm4(fal[mt], uAl + mt * (16 * SAS * 2) + ks * 32);
            }
#pragma unroll
            for (int np = 0; np < 2; np++) {
                ldsm4(fbh[np], uBh + np * (16 * SAS * 2) + ks * 32);
                ldsm4(fbl[np], uBl + np * (16 * SAS * 2) + ks * 32);
            }
#pragma unroll
            for (int mt = 0; mt < 4; mt++)
#pragma unroll
                for (int nt = 0; nt < 4; nt++) {
                    const uint32_t* b_h = &fbh[nt >> 1][(nt & 1) * 2];
                    const uint32_t* b_l = &fbl[nt >> 1][(nt & 1) * 2];
                    mma16816(acc[mt][nt], fah[mt], b_h);
                    mma16816(acc[mt][nt], fal[mt], b_h);
                    mma16816(acc[mt][nt], fah[mt], b_l);
                }
        }
        __syncthreads();
        if (more) SSTORE();
        __syncthreads();
    }

    // ---- epilogue ----
    const int g = lane >> 2, tg = lane & 3;
#pragma unroll
    for (int mt = 0; mt < 4; mt++) {
        const int mrow = m0 + wm * 64 + mt * 16 + g;
#pragma unroll
        for (int nt = 0; nt < 4; nt++) {
            const int ncol = n0 + wn * 32 + nt * 8 + tg * 2;
            float2 v0 = {acc[mt][nt][0], acc[mt][nt][1]};
            float2 v1 = {acc[mt][nt][2], acc[mt][nt][3]};
            *(float2*)(C + (size_t)mrow * N + ncol)       = v0;
            *(float2*)(C + (size_t)(mrow + 8) * N + ncol) = v1;
        }
    }
#undef GLOAD
#undef SSTORE
}

// ---------------------------------------------------------------------------
// RoPE (matches reference)
// ---------------------------------------------------------------------------
__global__ void rope_kernel(float* __restrict__ X, const int* __restrict__ posp,
                            int nheads, int total)
{
    int idx = blockIdx.x * blockDim.x + threadIdx.x;
    if (idx >= total) return;
    int p   = idx & 63;
    int h   = (idx >> 6) % nheads;
    int row = idx / (64 * nheads);
    int t   = row % T_;
    float pos = (float)(posp[0] + t);

    float* base = X + (size_t)row * (nheads * HD) + h * HD;
    float x1 = base[p];
    float x2 = base[p + 64];

    const float LN1E4 = 9.210340371976184f;
    float e1 = (float)(2 * (p >> 1)) * (1.0f / 128.0f);
    float e2 = e1 + 0.5f;
    float f1 = __expf(-e1 * LN1E4);
    float f2 = __expf(-e2 * LN1E4);
    float a1 = pos * f1;
    float a2 = pos * f2;

    base[p]      = x1 * cosf(a1) - x2 * sinf(a1);
    base[p + 64] = x2 * cosf(a2) + x1 * sinf(a2);
}

// ---------------------------------------------------------------------------
// Flash attention fp32 (FFMA2, unchanged from R2)
// ---------------------------------------------------------------------------
#define QPAD 132
#define PPAD 65
#define FLASH_SMEM ((3 * 64 * QPAD + 64 * PPAD) * 4)

extern __shared__ float fsm[];

__global__ __launch_bounds__(256) void flash_kernel(
    const float* __restrict__ Q, const float* __restrict__ Kg,
    const float* __restrict__ Vg, float* __restrict__ Y)
{
    float* Qs = fsm;
    float* Ks = Qs + 64 * QPAD;
    float* Vs = Ks + 64 * QPAD;
    float* Ps = Vs + 64 * QPAD;

    const int tid = threadIdx.x;
    const int qt = blockIdx.x, h = blockIdx.y, b = blockIdx.z;
    const int kvh = h >> 2;
    const int ty = tid >> 4, tx = tid & 15;

    const int qstride = C_;
    const int kstride = KVD;

    const float* Qb = Q  + ((size_t)b * T_ + (size_t)qt * 64) * qstride + h * HD;
    const float* Kb = Kg + ((size_t)b * T_) * kstride + kvh * HD;
    const float* Vb = Vg + ((size_t)b * T_) * kstride + kvh * HD;

    for (int i = tid; i < 64 * 32; i += 256) {
        int r = i >> 5, c4 = (i & 31) << 2;
        *(float4*)&Qs[r * QPAD + c4] = *(const float4*)(Qb + (size_t)r * qstride + c4);
    }

    float m[4], l[4];
    u64 o2[4][4];
#pragma unroll
    for (int r = 0; r < 4; r++) {
        m[r] = -INFINITY; l[r] = 0.0f;
#pragma unroll
        for (int c = 0; c < 4; c++) o2[r][c] = 0ull;
    }

    const float scale = 0.08838834764831845f;
    const int qg0 = qt * 64 + ty * 4;

    for (int kt = 0; kt <= qt; ++kt) {
        const float* Kt = Kb + (size_t)kt * 64 * kstride;
        const float* Vt = Vb + (size_t)kt * 64 * kstride;
        for (int i = tid; i < 64 * 32; i += 256) {
            int r = i >> 5, c4 = (i & 31) << 2;
            *(float4*)&Ks[r * QPAD + c4] = *(const float4*)(Kt + (size_t)r * kstride + c4);
            *(float4*)&Vs[r * QPAD + c4] = *(const float4*)(Vt + (size_t)r * kstride + c4);
        }
        __syncthreads();

        u64 s2[4][4];
#pragma unroll
        for (int r = 0; r < 4; r++)
#pragma unroll
            for (int c = 0; c < 4; c++) s2[r][c] = 0ull;

        for (int k4 = 0; k4 < 128; k4 += 4) {
            u64 qp[4][2], kp[4][2];
#pragma unroll
            for (int r = 0; r < 4; r++) {
                float4 qv = *(const float4*)&Qs[(ty * 4 + r) * QPAD + k4];
                qp[r][0] = pack2(qv.x, qv.y);
                qp[r][1] = pack2(qv.z, qv.w);
            }
#pragma unroll
            for (int ci = 0; ci < 4; ci++) {
                float4 kv = *(const float4*)&Ks[(tx + 16 * ci) * QPAD + k4];
                kp[ci][0] = pack2(kv.x, kv.y);
                kp[ci][1] = pack2(kv.z, kv.w);
            }
#pragma unroll
            for (int r = 0; r < 4; r++)
#pragma unroll
                for (int ci = 0; ci < 4; ci++) {
                    fma2(s2[r][ci], qp[r][0], kp[ci][0]);
                    fma2(s2[r][ci], qp[r][1], kp[ci][1]);
                }
        }

        float s[4][4];
        const int kg0 = kt * 64;
#pragma unroll
        for (int r = 0; r < 4; r++)
#pragma unroll
            for (int ci = 0; ci < 4; ci++) {
                float lo, hi;
                unpack2(s2[r][ci], lo, hi);
                int kg = kg0 + tx + 16 * ci;
                s[r][ci] = (kg <= qg0 + r) ? (lo + hi) * scale : -1e30f;
            }

#pragma unroll
        for (int r = 0; r < 4; r++) {
            float tm = fmaxf(fmaxf(s[r][0], s[r][1]), fmaxf(s[r][2], s[r][3]));
#pragma unroll
            for (int off = 8; off > 0; off >>= 1)
                tm = fmaxf(tm, __shfl_xor_sync(0xffffffffu, tm, off));
            float mn = fmaxf(m[r], tm);
            float fac = __expf(m[r] - mn);
            float ts = 0.0f;
#pragma unroll
            for (int ci = 0; ci < 4; ci++) {
                float p = __expf(s[r][ci] - mn);
                s[r][ci] = p;
                ts += p;
            }
#pragma unroll
            for (int off = 8; off > 0; off >>= 1)
                ts += __shfl_xor_sync(0xffffffffu, ts, off);
            l[r] = l[r] * fac + ts;
            m[r] = mn;
            u64 facp = pack2(fac, fac);
#pragma unroll
            for (int c = 0; c < 4; c++) mul2(o2[r][c], facp);
#pragma unroll
            for (int ci = 0; ci < 4; ci++)
                Ps[(ty * 4 + r) * PPAD + tx + 16 * ci] = s[r][ci];
        }
        __syncthreads();

        for (int kk = 0; kk < 64; kk++) {
            u64 pp[4];
#pragma unroll
            for (int r = 0; r < 4; r++) {
                float p = Ps[(ty * 4 + r) * PPAD + kk];
                pp[r] = pack2(p, p);
            }
            float4 v0 = *(const float4*)&Vs[kk * QPAD + tx * 8];
            float4 v1 = *(const float4*)&Vs[kk * QPAD + tx * 8 + 4];
            u64 vv[4];
            vv[0] = pack2(v0.x, v0.y);
            vv[1] = pack2(v0.z, v0.w);
            vv[2] = pack2(v1.x, v1.y);
            vv[3] = pack2(v1.z, v1.w);
#pragma unroll
            for (int r = 0; r < 4; r++) {
                fma2(o2[r][0], pp[r], vv[0]);
                fma2(o2[r][1], pp[r], vv[1]);
                fma2(o2[r][2], pp[r], vv[2]);
                fma2(o2[r][3], pp[r], vv[3]);
            }
        }
        __syncthreads();
    }

#pragma unroll
    for (int r = 0; r < 4; r++) {
        float inv = 1.0f / l[r];
        u64 invp = pack2(inv, inv);
        float* dst = Y + ((size_t)b * T_ + (size_t)(qt * 64 + ty * 4 + r)) * C_
                       + h * HD + tx * 8;
        float4 w0, w1;
        mul2(o2[r][0], invp); mul2(o2[r][1], invp);
        mul2(o2[r][2], invp); mul2(o2[r][3], invp);
        unpack2(o2[r][0], w0.x, w0.y);
        unpack2(o2[r][1], w0.z, w0.w);
        unpack2(o2[r][2], w1.x, w1.y);
        unpack2(o2[r][3], w1.z, w1.w);
        *(float4*)(dst)     = w0;
        *(float4*)(dst + 4) = w1;
    }
}

// ---------------------------------------------------------------------------
extern "C" void kernel_launch(void* const* d_in, const int* in_sizes, int n_in,
                              void* d_out, int out_size)
{
    const float* x  = (const float*)d_in[0];
    const float* Wq = (const float*)d_in[1];
    const float* Wk = (const float*)d_in[2];
    const float* Wv = (const float*)d_in[3];
    const float* Wo = (const float*)d_in[4];
    const int*  pos = (const int*)d_in[5];
    float* out = (float*)d_out;

    float *q, *k, *v, *y;
    cudaGetSymbolAddress((void**)&q, g_q);
    cudaGetSymbolAddress((void**)&k, g_k);
    cudaGetSymbolAddress((void**)&v, g_v);
    cudaGetSymbolAddress((void**)&y, g_y);
    __nv_bfloat16 *xh, *xl, *yh, *yl, *wqh, *wql, *wkh, *wkl, *wvh, *wvl, *woh, *wol;
    cudaGetSymbolAddress((void**)&xh, s_xh);   cudaGetSymbolAddress((void**)&xl, s_xl);
    cudaGetSymbolAddress((void**)&yh, s_yh);   cudaGetSymbolAddress((void**)&yl, s_yl);
    cudaGetSymbolAddress((void**)&wqh, s_wqh); cudaGetSymbolAddress((void**)&wql, s_wql);
    cudaGetSymbolAddress((void**)&wkh, s_wkh); cudaGetSymbolAddress((void**)&wkl, s_wkl);
    cudaGetSymbolAddress((void**)&wvh, s_wvh); cudaGetSymbolAddress((void**)&wvl, s_wvl);
    cudaGetSymbolAddress((void**)&woh, s_woh); cudaGetSymbolAddress((void**)&wol, s_wol);

    cudaFuncSetAttribute(flash_kernel, cudaFuncAttributeMaxDynamicSharedMemorySize,
                         FLASH_SMEM);

    // split x
    {
        int n4 = M_ * C_ / 4;
        split_kernel<<<(n4 + 255) / 256, 256>>>(x, xh, xl, n4);
    }
    // transpose+split weights
    transpose_split_kernel<<<dim3(C_ / 32,  C_ / 32), dim3(32, 8)>>>(Wq, wqh, wql, C_, C_);
    transpose_split_kernel<<<dim3(KVD / 32, C_ / 32), dim3(32, 8)>>>(Wk, wkh, wkl, C_, KVD);
    transpose_split_kernel<<<dim3(KVD / 32, C_ / 32), dim3(32, 8)>>>(Wv, wvh, wvl, C_, KVD);
    transpose_split_kernel<<<dim3(C_ / 32,  C_ / 32), dim3(32, 8)>>>(Wo, woh, wol, C_, C_);

    // projections (tensor cores via mma.sync)
    gemm_mma<<<dim3(C_ / 128,  M_ / 128), 256>>>(xh, xl, wqh, wql, q, C_,  C_);
    gemm_mma<<<dim3(KVD / 128, M_ / 128), 256>>>(xh, xl, wkh, wkl, k, KVD, C_);
    gemm_mma<<<dim3(KVD / 128, M_ / 128), 256>>>(xh, xl, wvh, wvl, v, KVD, C_);

    // RoPE
    int qp = M_ * NH * 64;
    rope_kernel<<<(qp + 255) / 256, 256>>>(q, pos, NH, qp);
    int kp = M_ * NKV * 64;
    rope_kernel<<<(kp + 255) / 256, 256>>>(k, pos, NKV, kp);

    // attention
    flash_kernel<<<dim3(T_ / 64, NH, B_), 256, FLASH_SMEM>>>(q, k, v, y);

    // split y, output projection
    {
        int n4 = M_ * C_ / 4;
        split_kernel<<<(n4 + 255) / 256, 256>>>(y, yh, yl, n4);
    }
    gemm_mma<<<dim3(C_ / 128, M_ / 128), 256>>>(yh, yl, woh, wol, out, C_, C_);
}

// round 5
// speedup vs baseline: 3.2323x; 1.9507x over previous
#include <cuda_runtime.h>
#include <cuda_bf16.h>
#include <cuda_fp16.h>
#include <math.h>
#include <stdint.h>

typedef unsigned long long u64;

#define B_   4
#define T_   2048
#define C_   2048
#define NH   16
#define NKV  4
#define HD   128
#define KVD  (NKV*HD)   // 512
#define M_   (B_*T_)    // 8192

// ---------------- scratch (__device__ globals; no allocs allowed) ----------
__device__ float g_q[(size_t)M_ * C_];
__device__ float g_k[(size_t)M_ * KVD];
__device__ float g_v[(size_t)M_ * KVD];

__device__ __nv_bfloat16 s_xh[(size_t)M_ * C_],  s_xl[(size_t)M_ * C_];
__device__ __nv_bfloat16 s_yh[(size_t)M_ * C_],  s_yl[(size_t)M_ * C_];
__device__ __nv_bfloat16 s_wqh[(size_t)C_ * C_], s_wql[(size_t)C_ * C_];
__device__ __nv_bfloat16 s_wkh[(size_t)KVD * C_], s_wkl[(size_t)KVD * C_];
__device__ __nv_bfloat16 s_wvh[(size_t)KVD * C_], s_wvl[(size_t)KVD * C_];
__device__ __nv_bfloat16 s_woh[(size_t)C_ * C_], s_wol[(size_t)C_ * C_];

// ---------------- helpers ---------------------------------------------------
__device__ __forceinline__ uint32_t smem_u32(const void* p) {
    uint32_t a;
    asm("{ .reg .u64 t; cvta.to.shared.u64 t, %1; cvt.u32.u64 %0, t; }"
        : "=r"(a) : "l"(p));
    return a;
}
__device__ __forceinline__ void ldsm4(uint32_t* r, uint32_t addr) {
    asm volatile("ldmatrix.sync.aligned.m8n8.x4.shared.b16 {%0,%1,%2,%3}, [%4];"
                 : "=r"(r[0]), "=r"(r[1]), "=r"(r[2]), "=r"(r[3]) : "r"(addr));
}
__device__ __forceinline__ void ldsm4t(uint32_t* r, uint32_t addr) {
    asm volatile("ldmatrix.sync.aligned.m8n8.x4.trans.shared.b16 {%0,%1,%2,%3}, [%4];"
                 : "=r"(r[0]), "=r"(r[1]), "=r"(r[2]), "=r"(r[3]) : "r"(addr));
}
__device__ __forceinline__ void mma16816(float* c, const uint32_t* a,
                                         const uint32_t* b) {
    asm volatile(
        "mma.sync.aligned.m16n8k16.row.col.f32.bf16.bf16.f32 "
        "{%0,%1,%2,%3}, {%4,%5,%6,%7}, {%8,%9}, {%0,%1,%2,%3};"
        : "+f"(c[0]), "+f"(c[1]), "+f"(c[2]), "+f"(c[3])
        : "r"(a[0]), "r"(a[1]), "r"(a[2]), "r"(a[3]), "r"(b[0]), "r"(b[1]));
}
__device__ __forceinline__ void mma16816h(float* c, const uint32_t* a,
                                          const uint32_t* b) {
    asm volatile(
        "mma.sync.aligned.m16n8k16.row.col.f32.f16.f16.f32 "
        "{%0,%1,%2,%3}, {%4,%5,%6,%7}, {%8,%9}, {%0,%1,%2,%3};"
        : "+f"(c[0]), "+f"(c[1]), "+f"(c[2]), "+f"(c[3])
        : "r"(a[0]), "r"(a[1]), "r"(a[2]), "r"(a[3]), "r"(b[0]), "r"(b[1]));
}

// ---------------------------------------------------------------------------
// split: fp32 -> (bf16 hi, bf16 lo), vectorized x4
// ---------------------------------------------------------------------------
__global__ void split_kernel(const float* __restrict__ X,
                             __nv_bfloat16* __restrict__ H,
                             __nv_bfloat16* __restrict__ L, int n4)
{
    int i = blockIdx.x * blockDim.x + threadIdx.x;
    if (i >= n4) return;
    float4 v = ((const float4*)X)[i];
    float vv[4] = {v.x, v.y, v.z, v.w};
    __nv_bfloat162 h0, h1, l0, l1;
    __nv_bfloat16 h[4], l[4];
#pragma unroll
    for (int j = 0; j < 4; j++) {
        h[j] = __float2bfloat16(vv[j]);
        l[j] = __float2bfloat16(vv[j] - __bfloat162float(h[j]));
    }
    h0.x = h[0]; h0.y = h[1]; h1.x = h[2]; h1.y = h[3];
    l0.x = l[0]; l0.y = l[1]; l1.x = l[2]; l1.y = l[3];
    ((__nv_bfloat162*)H)[2 * i]     = h0;
    ((__nv_bfloat162*)H)[2 * i + 1] = h1;
    ((__nv_bfloat162*)L)[2 * i]     = l0;
    ((__nv_bfloat162*)L)[2 * i + 1] = l1;
}

// ---------------------------------------------------------------------------
// transpose + split: W[K,N] fp32 -> Th/Tl [N,K] bf16
// ---------------------------------------------------------------------------
__global__ void transpose_split_kernel(const float* __restrict__ W,
                                       __nv_bfloat16* __restrict__ Th,
                                       __nv_bfloat16* __restrict__ Tl,
                                       int K, int N)
{
    __shared__ float t[32][33];
    int n0 = blockIdx.x * 32, k0 = blockIdx.y * 32;
    int tx = threadIdx.x, ty = threadIdx.y;  // 32 x 8
#pragma unroll
    for (int j = 0; j < 4; j++)
        t[ty + 8 * j][tx] = W[(size_t)(k0 + ty + 8 * j) * N + n0 + tx];
    __syncthreads();
#pragma unroll
    for (int j = 0; j < 4; j++) {
        float v = t[tx][ty + 8 * j];
        __nv_bfloat16 h = __float2bfloat16(v);
        __nv_bfloat16 l = __float2bfloat16(v - __bfloat162float(h));
        size_t o = (size_t)(n0 + ty + 8 * j) * K + k0 + tx;
        Th[o] = h;
        Tl[o] = l;
    }
}

// ---------------------------------------------------------------------------
// bf16-split GEMM via mma.sync (HMMA) — unchanged from R4 (proven)
// ---------------------------------------------------------------------------
#define SAS 40

__global__ __launch_bounds__(256) void gemm_mma(
    const __nv_bfloat16* __restrict__ Ah, const __nv_bfloat16* __restrict__ Al,
    const __nv_bfloat16* __restrict__ Bh, const __nv_bfloat16* __restrict__ Bl,
    float* __restrict__ C, int N, int K)
{
    __shared__ __nv_bfloat16 sAh[128 * SAS], sAl[128 * SAS];
    __shared__ __nv_bfloat16 sBh[128 * SAS], sBl[128 * SAS];

    const int tid = threadIdx.x;
    const int lane = tid & 31, wid = tid >> 5;
    const int wm = wid & 1, wn = wid >> 1;
    const int m0 = blockIdx.y * 128, n0 = blockIdx.x * 128;

    const int ldrow = tid >> 1, ldhalf = tid & 1;
    const __nv_bfloat16* gAh = Ah + (size_t)(m0 + ldrow) * K + ldhalf * 16;
    const __nv_bfloat16* gAl = Al + (size_t)(m0 + ldrow) * K + ldhalf * 16;
    const __nv_bfloat16* gBh = Bh + (size_t)(n0 + ldrow) * K + ldhalf * 16;
    const __nv_bfloat16* gBl = Bl + (size_t)(n0 + ldrow) * K + ldhalf * 16;
    char* stAh = (char*)sAh + (ldrow * SAS + ldhalf * 16) * 2;
    char* stAl = (char*)sAl + (ldrow * SAS + ldhalf * 16) * 2;
    char* stBh = (char*)sBh + (ldrow * SAS + ldhalf * 16) * 2;
    char* stBl = (char*)sBl + (ldrow * SAS + ldhalf * 16) * 2;

    const int mid = lane >> 3, rin = lane & 7;
    const uint32_t aoff =
        ((wm * 64 + (mid & 1) * 8 + rin) * SAS + (mid >> 1) * 8) * 2;
    const uint32_t boff =
        ((wn * 32 + (mid >> 1) * 8 + rin) * SAS + (mid & 1) * 8) * 2;
    const uint32_t uAh = smem_u32(sAh) + aoff, uAl = smem_u32(sAl) + aoff;
    const uint32_t uBh = smem_u32(sBh) + boff, uBl = smem_u32(sBl) + boff;

    float acc[4][4][4];
#pragma unroll
    for (int mt = 0; mt < 4; mt++)
#pragma unroll
        for (int nt = 0; nt < 4; nt++)
#pragma unroll
            for (int j = 0; j < 4; j++) acc[mt][nt][j] = 0.0f;

    uint4 rah[2], ral[2], rbh[2], rbl[2];

#define GLOAD(k0)                                            \
    {                                                        \
        rah[0] = *(const uint4*)(gAh + (k0));                \
        rah[1] = *(const uint4*)(gAh + (k0) + 8);            \
        ral[0] = *(const uint4*)(gAl + (k0));                \
        ral[1] = *(const uint4*)(gAl + (k0) + 8);            \
        rbh[0] = *(const uint4*)(gBh + (k0));                \
        rbh[1] = *(const uint4*)(gBh + (k0) + 8);            \
        rbl[0] = *(const uint4*)(gBl + (k0));                \
        rbl[1] = *(const uint4*)(gBl + (k0) + 8);            \
    }
#define SSTORE()                                             \
    {                                                        \
        *(uint4*)(stAh) = rah[0]; *(uint4*)(stAh + 16) = rah[1]; \
        *(uint4*)(stAl) = ral[0]; *(uint4*)(stAl + 16) = ral[1]; \
        *(uint4*)(stBh) = rbh[0]; *(uint4*)(stBh + 16) = rbh[1]; \
        *(uint4*)(stBl) = rbl[0]; *(uint4*)(stBl + 16) = rbl[1]; \
    }

    GLOAD(0);
    SSTORE();
    __syncthreads();

    const int nch = K / 32;
    for (int ch = 0; ch < nch; ch++) {
        const bool more = (ch + 1 < nch);
        if (more) GLOAD((ch + 1) * 32);

#pragma unroll
        for (int ks = 0; ks < 2; ks++) {
            uint32_t fah[4][4], fal[4][4], fbh[2][4], fbl[2][4];
#pragma unroll
            for (int mt = 0; mt < 4; mt++) {
                ldsm4(fah[mt], uAh + mt * (16 * SAS * 2) + ks * 32);
                ldsm4(fal[mt], uAl + mt * (16 * SAS * 2) + ks * 32);
            }
#pragma unroll
            for (int np = 0; np < 2; np++) {
                ldsm4(fbh[np], uBh + np * (16 * SAS * 2) + ks * 32);
                ldsm4(fbl[np], uBl + np * (16 * SAS * 2) + ks * 32);
            }
#pragma unroll
            for (int mt = 0; mt < 4; mt++)
#pragma unroll
                for (int nt = 0; nt < 4; nt++) {
                    const uint32_t* b_h = &fbh[nt >> 1][(nt & 1) * 2];
                    const uint32_t* b_l = &fbl[nt >> 1][(nt & 1) * 2];
                    mma16816(acc[mt][nt], fah[mt], b_h);
                    mma16816(acc[mt][nt], fal[mt], b_h);
                    mma16816(acc[mt][nt], fah[mt], b_l);
                }
        }
        __syncthreads();
        if (more) SSTORE();
        __syncthreads();
    }

    const int g = lane >> 2, tg = lane & 3;
#pragma unroll
    for (int mt = 0; mt < 4; mt++) {
        const int mrow = m0 + wm * 64 + mt * 16 + g;
#pragma unroll
        for (int nt = 0; nt < 4; nt++) {
            const int ncol = n0 + wn * 32 + nt * 8 + tg * 2;
            float2 v0 = {acc[mt][nt][0], acc[mt][nt][1]};
            float2 v1 = {acc[mt][nt][2], acc[mt][nt][3]};
            *(float2*)(C + (size_t)mrow * N + ncol)       = v0;
            *(float2*)(C + (size_t)(mrow + 8) * N + ncol) = v1;
        }
    }
#undef GLOAD
#undef SSTORE
}

// ---------------------------------------------------------------------------
// RoPE (matches reference)
// ---------------------------------------------------------------------------
__global__ void rope_kernel(float* __restrict__ X, const int* __restrict__ posp,
                            int nheads, int total)
{
    int idx = blockIdx.x * blockDim.x + threadIdx.x;
    if (idx >= total) return;
    int p   = idx & 63;
    int h   = (idx >> 6) % nheads;
    int row = idx / (64 * nheads);
    int t   = row % T_;
    float pos = (float)(posp[0] + t);

    float* base = X + (size_t)row * (nheads * HD) + h * HD;
    float x1 = base[p];
    float x2 = base[p + 64];

    const float LN1E4 = 9.210340371976184f;
    float e1 = (float)(2 * (p >> 1)) * (1.0f / 128.0f);
    float e2 = e1 + 0.5f;
    float f1 = __expf(-e1 * LN1E4);
    float f2 = __expf(-e2 * LN1E4);
    float a1 = pos * f1;
    float a2 = pos * f2;

    base[p]      = x1 * cosf(a1) - x2 * sinf(a1);
    base[p + 64] = x2 * cosf(a2) + x1 * sinf(a2);
}

// ---------------------------------------------------------------------------
// Flash attention on mma.sync.
// CTA: 128 q-rows x (head, batch); 8 warps x 16 rows. K tiles of 64.
// QK^T: bf16 hi/lo 3-pass. P.V: fp16 single pass, P packed from C-frags.
// K/V converted fp32->bf16(hi/lo)/fp16 into smem, row stride 136 elems.
// Output written directly as bf16 hi/lo splits (feeds Wo gemm).
// ---------------------------------------------------------------------------
#define SKP 136
#define FL_SMEM (3 * 64 * SKP * 2)   // Kh, Kl (bf16) + Vh (fp16)

extern __shared__ char flsm[];

__global__ __launch_bounds__(256) void flash_mma(
    const float* __restrict__ Q, const float* __restrict__ Kg,
    const float* __restrict__ Vg,
    __nv_bfloat16* __restrict__ Yh, __nv_bfloat16* __restrict__ Yl)
{
    __nv_bfloat16* sKh = (__nv_bfloat16*)flsm;
    __nv_bfloat16* sKl = sKh + 64 * SKP;
    __half*        sVh = (__half*)(sKl + 64 * SKP);

    const int tid = threadIdx.x, lane = tid & 31, w = tid >> 5;
    const int qb = blockIdx.x, h = blockIdx.y, b = blockIdx.z;
    const int kvh = h >> 2;
    const int g = lane >> 2, tg = lane & 3;
    const int mid = lane >> 3, rin = lane & 7;
    const int qrow0 = qb * 128 + w * 16;

    // ---- load resident Q fragments (bf16 hi/lo) straight from gmem ----
    uint32_t qh[8][4], ql[8][4];
    {
        const float* Qb = Q + ((size_t)b * T_ + qrow0) * C_ + h * HD;
#pragma unroll
        for (int kc = 0; kc < 8; kc++) {
#pragma unroll
            for (int fr = 0; fr < 4; fr++) {
                int r = g + (fr & 1) * 8;
                int c = kc * 16 + tg * 2 + (fr >> 1) * 8;
                float2 v = *(const float2*)(Qb + (size_t)r * C_ + c);
                __nv_bfloat162 hi = __float22bfloat162_rn(v);
                float2 hf = __bfloat1622float2(hi);
                __nv_bfloat162 lo = __float22bfloat162_rn(
                    make_float2(v.x - hf.x, v.y - hf.y));
                qh[kc][fr] = *reinterpret_cast<uint32_t*>(&hi);
                ql[kc][fr] = *reinterpret_cast<uint32_t*>(&lo);
            }
        }
    }

    float o[16][4];
#pragma unroll
    for (int nt = 0; nt < 16; nt++)
#pragma unroll
        for (int j = 0; j < 4; j++) o[nt][j] = 0.0f;
    float m0 = -INFINITY, m1 = -INFINITY, l0 = 0.0f, l1 = 0.0f;

    const float cscale = 0.08838834764831845f;  // 1/sqrt(128)
    const int rg0 = qrow0 + g, rg1 = rg0 + 8;
    const int ktmax = 2 * qb + 2;

    const float* Kt0 = Kg + (size_t)b * T_ * KVD + kvh * HD;
    const float* Vt0 = Vg + (size_t)b * T_ * KVD + kvh * HD;

    const uint32_t uKh = smem_u32(sKh), uKl = smem_u32(sKl), uVh = smem_u32(sVh);
    // ldmatrix base offsets (non-trans for K; trans for V)
    const uint32_t kfrag = (((mid >> 1) * 8 + rin) * SKP + (mid & 1) * 8) * 2;
    const uint32_t vfrag = (((mid & 1) * 8 + rin) * SKP + (mid >> 1) * 8) * 2;

    for (int kt = 0; kt < ktmax; kt++) {
        __syncthreads();
        // ---- load + convert K (bf16 hi/lo) and V (fp16) tiles ----
        {
            const float* Kt = Kt0 + (size_t)kt * 64 * KVD;
            const float* Vt = Vt0 + (size_t)kt * 64 * KVD;
#pragma unroll
            for (int it = 0; it < 8; it++) {
                int i = tid + it * 256;
                int r = i >> 5, c4 = (i & 31) << 2;
                float4 kv = *(const float4*)(Kt + (size_t)r * KVD + c4);
                __nv_bfloat162 h0 = __float22bfloat162_rn(make_float2(kv.x, kv.y));
                __nv_bfloat162 h1 = __float22bfloat162_rn(make_float2(kv.z, kv.w));
                float2 f0 = __bfloat1622float2(h0), f1 = __bfloat1622float2(h1);
                __nv_bfloat162 l0v = __float22bfloat162_rn(
                    make_float2(kv.x - f0.x, kv.y - f0.y));
                __nv_bfloat162 l1v = __float22bfloat162_rn(
                    make_float2(kv.z - f1.x, kv.w - f1.y));
                *(uint32_t*)(sKh + r * SKP + c4)     = *(uint32_t*)&h0;
                *(uint32_t*)(sKh + r * SKP + c4 + 2) = *(uint32_t*)&h1;
                *(uint32_t*)(sKl + r * SKP + c4)     = *(uint32_t*)&l0v;
                *(uint32_t*)(sKl + r * SKP + c4 + 2) = *(uint32_t*)&l1v;
                float4 vv = *(const float4*)(Vt + (size_t)r * KVD + c4);
                __half2 v0 = __floats2half2_rn(vv.x, vv.y);
                __half2 v1 = __floats2half2_rn(vv.z, vv.w);
                *(uint32_t*)(sVh + r * SKP + c4)     = *(uint32_t*)&v0;
                *(uint32_t*)(sVh + r * SKP + c4 + 2) = *(uint32_t*)&v1;
            }
        }
        __syncthreads();

        if (kt * 64 > qrow0 + 15) continue;          // fully masked for this warp
        const bool needmask = (kt * 64 + 63 > qrow0);

        // ---- S = Q K^T (3-pass bf16 split) ----
        float s[8][4];
#pragma unroll
        for (int nt = 0; nt < 8; nt++)
#pragma unroll
            for (int j = 0; j < 4; j++) s[nt][j] = 0.0f;

#pragma unroll
        for (int kc = 0; kc < 8; kc++) {
            uint32_t bt[4][4];
#pragma unroll
            for (int nt2 = 0; nt2 < 4; nt2++)
                ldsm4(bt[nt2], uKh + kfrag + (nt2 * 16 * SKP + kc * 16) * 2);
#pragma unroll
            for (int nt = 0; nt < 8; nt++) {
                const uint32_t* bb = &bt[nt >> 1][(nt & 1) * 2];
                mma16816(s[nt], qh[kc], bb);
                mma16816(s[nt], ql[kc], bb);
            }
#pragma unroll
            for (int nt2 = 0; nt2 < 4; nt2++)
                ldsm4(bt[nt2], uKl + kfrag + (nt2 * 16 * SKP + kc * 16) * 2);
#pragma unroll
            for (int nt = 0; nt < 8; nt++)
                mma16816(s[nt], qh[kc], &bt[nt >> 1][(nt & 1) * 2]);
        }

        // ---- scale + mask ----
#pragma unroll
        for (int nt = 0; nt < 8; nt++) {
#pragma unroll
            for (int j = 0; j < 4; j++) s[nt][j] *= cscale;
            if (needmask) {
                int c0 = kt * 64 + nt * 8 + tg * 2;
                if (c0 > rg0)     s[nt][0] = -1e30f;
                if (c0 + 1 > rg0) s[nt][1] = -1e30f;
                if (c0 > rg1)     s[nt][2] = -1e30f;
                if (c0 + 1 > rg1) s[nt][3] = -1e30f;
            }
        }

        // ---- online softmax on fragments ----
        float mn0 = m0, mn1 = m1;
#pragma unroll
        for (int nt = 0; nt < 8; nt++) {
            mn0 = fmaxf(mn0, fmaxf(s[nt][0], s[nt][1]));
            mn1 = fmaxf(mn1, fmaxf(s[nt][2], s[nt][3]));
        }
        mn0 = fmaxf(mn0, __shfl_xor_sync(0xffffffffu, mn0, 1));
        mn0 = fmaxf(mn0, __shfl_xor_sync(0xffffffffu, mn0, 2));
        mn1 = fmaxf(mn1, __shfl_xor_sync(0xffffffffu, mn1, 1));
        mn1 = fmaxf(mn1, __shfl_xor_sync(0xffffffffu, mn1, 2));
        float fac0 = __expf(m0 - mn0), fac1 = __expf(m1 - mn1);
        m0 = mn0; m1 = mn1;

        uint32_t pa[4][4];
        float ps0 = 0.0f, ps1 = 0.0f;
#pragma unroll
        for (int kk = 0; kk < 4; kk++) {
            int nt = 2 * kk;
            float p00 = __expf(s[nt][0] - m0),     p01 = __expf(s[nt][1] - m0);
            float p02 = __expf(s[nt][2] - m1),     p03 = __expf(s[nt][3] - m1);
            float p10 = __expf(s[nt + 1][0] - m0), p11 = __expf(s[nt + 1][1] - m0);
            float p12 = __expf(s[nt + 1][2] - m1), p13 = __expf(s[nt + 1][3] - m1);
            ps0 += p00 + p01 + p10 + p11;
            ps1 += p02 + p03 + p12 + p13;
            __half2 a0 = __floats2half2_rn(p00, p01);
            __half2 a1 = __floats2half2_rn(p02, p03);
            __half2 a2 = __floats2half2_rn(p10, p11);
            __half2 a3 = __floats2half2_rn(p12, p13);
            pa[kk][0] = *(uint32_t*)&a0;
            pa[kk][1] = *(uint32_t*)&a1;
            pa[kk][2] = *(uint32_t*)&a2;
            pa[kk][3] = *(uint32_t*)&a3;
        }
        l0 = l0 * fac0 + ps0;
        l1 = l1 * fac1 + ps1;

        // rescale O
#pragma unroll
        for (int nt = 0; nt < 16; nt++) {
            o[nt][0] *= fac0; o[nt][1] *= fac0;
            o[nt][2] *= fac1; o[nt][3] *= fac1;
        }

        // ---- O += P V (fp16) ----
#pragma unroll
        for (int kk = 0; kk < 4; kk++) {
            uint32_t vb[8][4];
#pragma unroll
            for (int np = 0; np < 8; np++)
                ldsm4t(vb[np], uVh + vfrag + (kk * 16 * SKP + np * 16) * 2);
#pragma unroll
            for (int nt = 0; nt < 16; nt++)
                mma16816h(o[nt], pa[kk], &vb[nt >> 1][(nt & 1) * 2]);
        }
    }

    // ---- finalize: reduce l across quad, normalize, split-store ----
    l0 += __shfl_xor_sync(0xffffffffu, l0, 1);
    l0 += __shfl_xor_sync(0xffffffffu, l0, 2);
    l1 += __shfl_xor_sync(0xffffffffu, l1, 1);
    l1 += __shfl_xor_sync(0xffffffffu, l1, 2);
    float inv0 = 1.0f / l0, inv1 = 1.0f / l1;

    size_t row0 = (size_t)b * T_ + rg0;
    size_t row1 = (size_t)b * T_ + rg1;
#pragma unroll
    for (int nt = 0; nt < 16; nt++) {
        int col = h * HD + nt * 8 + tg * 2;
        float2 v0 = {o[nt][0] * inv0, o[nt][1] * inv0};
        float2 v1 = {o[nt][2] * inv1, o[nt][3] * inv1};
        __nv_bfloat162 h0 = __float22bfloat162_rn(v0);
        __nv_bfloat162 h1 = __float22bfloat162_rn(v1);
        float2 f0 = __bfloat1622float2(h0), f1 = __bfloat1622float2(h1);
        __nv_bfloat162 e0 = __float22bfloat162_rn(make_float2(v0.x - f0.x, v0.y - f0.y));
        __nv_bfloat162 e1 = __float22bfloat162_rn(make_float2(v1.x - f1.x, v1.y - f1.y));
        *(uint32_t*)(Yh + row0 * C_ + col) = *(uint32_t*)&h0;
        *(uint32_t*)(Yh + row1 * C_ + col) = *(uint32_t*)&h1;
        *(uint32_t*)(Yl + row0 * C_ + col) = *(uint32_t*)&e0;
        *(uint32_t*)(Yl + row1 * C_ + col) = *(uint32_t*)&e1;
    }
}

// ---------------------------------------------------------------------------
extern "C" void kernel_launch(void* const* d_in, const int* in_sizes, int n_in,
                              void* d_out, int out_size)
{
    const float* x  = (const float*)d_in[0];
    const float* Wq = (const float*)d_in[1];
    const float* Wk = (const float*)d_in[2];
    const float* Wv = (const float*)d_in[3];
    const float* Wo = (const float*)d_in[4];
    const int*  pos = (const int*)d_in[5];
    float* out = (float*)d_out;

    float *q, *k, *v;
    cudaGetSymbolAddress((void**)&q, g_q);
    cudaGetSymbolAddress((void**)&k, g_k);
    cudaGetSymbolAddress((void**)&v, g_v);
    __nv_bfloat16 *xh, *xl, *yh, *yl, *wqh, *wql, *wkh, *wkl, *wvh, *wvl, *woh, *wol;
    cudaGetSymbolAddress((void**)&xh, s_xh);   cudaGetSymbolAddress((void**)&xl, s_xl);
    cudaGetSymbolAddress((void**)&yh, s_yh);   cudaGetSymbolAddress((void**)&yl, s_yl);
    cudaGetSymbolAddress((void**)&wqh, s_wqh); cudaGetSymbolAddress((void**)&wql, s_wql);
    cudaGetSymbolAddress((void**)&wkh, s_wkh); cudaGetSymbolAddress((void**)&wkl, s_wkl);
    cudaGetSymbolAddress((void**)&wvh, s_wvh); cudaGetSymbolAddress((void**)&wvl, s_wvl);
    cudaGetSymbolAddress((void**)&woh, s_woh); cudaGetSymbolAddress((void**)&wol, s_wol);

    cudaFuncSetAttribute(flash_mma, cudaFuncAttributeMaxDynamicSharedMemorySize,
                         FL_SMEM);

    // split x
    {
        int n4 = M_ * C_ / 4;
        split_kernel<<<(n4 + 255) / 256, 256>>>(x, xh, xl, n4);
    }
    // transpose+split weights
    transpose_split_kernel<<<dim3(C_ / 32,  C_ / 32), dim3(32, 8)>>>(Wq, wqh, wql, C_, C_);
    transpose_split_kernel<<<dim3(KVD / 32, C_ / 32), dim3(32, 8)>>>(Wk, wkh, wkl, C_, KVD);
    transpose_split_kernel<<<dim3(KVD / 32, C_ / 32), dim3(32, 8)>>>(Wv, wvh, wvl, C_, KVD);
    transpose_split_kernel<<<dim3(C_ / 32,  C_ / 32), dim3(32, 8)>>>(Wo, woh, wol, C_, C_);

    // projections (tensor cores via mma.sync)
    gemm_mma<<<dim3(C_ / 128,  M_ / 128), 256>>>(xh, xl, wqh, wql, q, C_,  C_);
    gemm_mma<<<dim3(KVD / 128, M_ / 128), 256>>>(xh, xl, wkh, wkl, k, KVD, C_);
    gemm_mma<<<dim3(KVD / 128, M_ / 128), 256>>>(xh, xl, wvh, wvl, v, KVD, C_);

    // RoPE
    int qp = M_ * NH * 64;
    rope_kernel<<<(qp + 255) / 256, 256>>>(q, pos, NH, qp);
    int kp = M_ * NKV * 64;
    rope_kernel<<<(kp + 255) / 256, 256>>>(k, pos, NKV, kp);

    // attention (tensor cores), writes bf16 hi/lo splits directly
    flash_mma<<<dim3(T_ / 128, NH, B_), 256, FL_SMEM>>>(q, k, v, yh, yl);

    // output projection
    gemm_mma<<<dim3(C_ / 128, M_ / 128), 256>>>(yh, yl, woh, wol, out, C_, C_);
}